// round 10
// baseline (speedup 1.0000x reference)
#include <cuda_runtime.h>
#include <cuda_bf16.h>
#include <math.h>

#define BB 64
#define LL 384
#define CC 512
#define HH 512
#define EE 256
#define NC 250
#define TT 127
#define KX 1280     // C + E + H
#define G4 2048     // 4*H

// ---------------- device scratch (no cudaMalloc allowed) ----------------
__device__ __align__(16) float g_srcfT[(size_t)BB * HH * LL];   // [b][h][l]
__device__ __align__(16) float g_Wt[(size_t)KX * G4];           // [k][u*4+g]
__device__ __align__(16) float g_bperm[G4];
__device__ __align__(16) float g_Wh2hT[HH * HH];                // [k][j]
__device__ __align__(16) float g_WgenT[HH * NC];                // [k][n]
__device__ __align__(16) float g_emb[(size_t)BB * TT * EE];
__device__ __align__(16) float g_hbuf[2][BB * HH];
__device__ __align__(16) float g_c[BB * HH];
__device__ __align__(16) float g_proj[BB * HH];
__device__ __align__(16) float g_ctx[BB * CC];
__device__ __align__(16) float g_hs[(size_t)BB * TT * HH];

// ---------------- math helpers ----------------
__device__ __forceinline__ float tanh_acc(float x) {
    float a = fabsf(x);
    float e = __expf(-2.0f * a);
    float r = __fdividef(1.0f - e, 1.0f + e);
    return copysignf(r, x);
}
__device__ __forceinline__ float sigm(float x) {
    return __fdividef(1.0f, 1.0f + __expf(-x));
}

// ---------------- prep kernels ----------------
__global__ void k_init() {
    int i = blockIdx.x * blockDim.x + threadIdx.x;
    if (i < BB * HH) { g_hbuf[0][i] = 0.f; g_hbuf[1][i] = 0.f; g_c[i] = 0.f; }
}

__global__ void k_prep_w(const float* __restrict__ W_ih, const float* __restrict__ b_ih,
                         const float* __restrict__ W_hh, const float* __restrict__ b_hh) {
    int idx = blockIdx.x * blockDim.x + threadIdx.x;
    if (idx >= KX * G4) return;
    int k = idx >> 11;
    int col = idx & (G4 - 1);
    int u = col >> 2;
    int g = col & 3;
    int row = g * HH + u;                      // PyTorch gate order i,f,g,o
    float v = (k < CC + EE) ? W_ih[(size_t)row * (CC + EE) + k]
                            : W_hh[(size_t)row * HH + (k - (CC + EE))];
    g_Wt[idx] = v;
    if (k == 0) g_bperm[col] = b_ih[row] + b_hh[row];
}

__global__ void k_prep_wh(const float* __restrict__ Wh2h) {
    int idx = blockIdx.x * blockDim.x + threadIdx.x;
    if (idx >= HH * HH) return;
    int k = idx >> 9, j = idx & (HH - 1);
    g_Wh2hT[idx] = Wh2h[j * HH + k];
}

__global__ void k_prep_wgen(const float* __restrict__ Wgen) {
    int idx = blockIdx.x * blockDim.x + threadIdx.x;
    if (idx >= HH * NC) return;
    int k = idx / NC, n = idx - k * NC;
    g_WgenT[idx] = Wgen[(size_t)n * HH + k];
}

__global__ void k_emb(const int* __restrict__ text, const float* __restrict__ emb_table) {
    int idx = blockIdx.x * blockDim.x + threadIdx.x;
    if (idx >= BB * TT * EE) return;
    int e = idx & (EE - 1);
    int bt = idx >> 8;
    int tok = text[bt];
    g_emb[idx] = emb_table[(size_t)tok * EE + e];
}

// src_featT[b][h][l] = sum_c Wi2h[h][c] * src[b][l][c]
// grid (L/64=6, H/64=8, B=64), 256 threads, 64x64 tile, KT=16, 4x4 microtile
__global__ __launch_bounds__(256) void k_srcfeat(const float* __restrict__ src,
                                                 const float* __restrict__ Wi2h) {
    __shared__ __align__(16) float Wsh[16][68];
    __shared__ __align__(16) float Ssh[16][68];
    int l0 = blockIdx.x * 64;
    int h0 = blockIdx.y * 64;
    int b  = blockIdx.z;
    int tid = threadIdx.x;
    int r  = tid >> 2;
    int kq = (tid & 3) << 2;
    int th = tid & 15;        // h micro index
    int tl = tid >> 4;        // l micro index
    float acc[4][4];
#pragma unroll
    for (int i = 0; i < 4; i++)
#pragma unroll
        for (int j = 0; j < 4; j++) acc[i][j] = 0.f;

    const float* srow = src + ((size_t)b * LL + l0 + r) * CC;
    const float* wrow = Wi2h + (size_t)(h0 + r) * CC;

    for (int k0 = 0; k0 < CC; k0 += 16) {
        float4 w4 = *(const float4*)(wrow + k0 + kq);
        float4 s4 = *(const float4*)(srow + k0 + kq);
        Wsh[kq + 0][r] = w4.x; Wsh[kq + 1][r] = w4.y; Wsh[kq + 2][r] = w4.z; Wsh[kq + 3][r] = w4.w;
        Ssh[kq + 0][r] = s4.x; Ssh[kq + 1][r] = s4.y; Ssh[kq + 2][r] = s4.z; Ssh[kq + 3][r] = s4.w;
        __syncthreads();
#pragma unroll
        for (int kk = 0; kk < 16; kk++) {
            float4 a4 = *(const float4*)&Wsh[kk][th << 2];
            float4 b4 = *(const float4*)&Ssh[kk][tl << 2];
            float av[4] = {a4.x, a4.y, a4.z, a4.w};
            float bv[4] = {b4.x, b4.y, b4.z, b4.w};
#pragma unroll
            for (int i = 0; i < 4; i++)
#pragma unroll
                for (int j = 0; j < 4; j++) acc[i][j] += av[i] * bv[j];
        }
        __syncthreads();
    }
#pragma unroll
    for (int i = 0; i < 4; i++) {
        float4 o4 = make_float4(acc[i][0], acc[i][1], acc[i][2], acc[i][3]);
        *(float4*)&g_srcfT[((size_t)b * HH + h0 + (th << 2) + i) * LL + l0 + (tl << 2)] = o4;
    }
}

// ---------------- per-step kernels ----------------
// proj[b][j] = sum_k h[b][k]*Wh2hT[k][j] + bh2h[j]
// grid 128: 32 j-tiles(16) x 4 b-tiles(16). 256 thr: j=tid&15, bloc=tid>>4
__global__ __launch_bounds__(256) void k_proj(const float* __restrict__ bh2h, int t) {
    __shared__ float hsh[16 * HH];
    int jt = blockIdx.x & 31;
    int bt = blockIdx.x >> 5;
    int tid = threadIdx.x;
    int j = jt * 16 + (tid & 15);
    int bloc = tid >> 4;
    const float* hin = g_hbuf[t & 1];
    for (int i = tid; i < 16 * HH; i += 256) hsh[i] = hin[bt * 16 * HH + i];
    __syncthreads();
    float acc = 0.f;
    const float* wp = g_Wh2hT + j;
    const float* hp = hsh + bloc * HH;
#pragma unroll 8
    for (int k = 0; k < HH; k++) acc += hp[k] * wp[(size_t)k * HH];
    int b = bt * 16 + bloc;
    g_proj[(b << 9) + j] = acc + bh2h[j];
}

// block reduce helpers (384 threads = 12 warps)
__device__ __forceinline__ float blk_red_max(float v, float* sm) {
#pragma unroll
    for (int o = 16; o; o >>= 1) v = fmaxf(v, __shfl_xor_sync(0xFFFFFFFFu, v, o));
    int w = threadIdx.x >> 5;
    if ((threadIdx.x & 31) == 0) sm[w] = v;
    __syncthreads();
    if (threadIdx.x < 32) {
        float x = (threadIdx.x < 12) ? sm[threadIdx.x] : -INFINITY;
#pragma unroll
        for (int o = 16; o; o >>= 1) x = fmaxf(x, __shfl_xor_sync(0xFFFFFFFFu, x, o));
        if (threadIdx.x == 0) sm[12] = x;
    }
    __syncthreads();
    float r = sm[12];
    __syncthreads();
    return r;
}
__device__ __forceinline__ float blk_red_sum(float v, float* sm) {
#pragma unroll
    for (int o = 16; o; o >>= 1) v += __shfl_xor_sync(0xFFFFFFFFu, v, o);
    int w = threadIdx.x >> 5;
    if ((threadIdx.x & 31) == 0) sm[w] = v;
    __syncthreads();
    if (threadIdx.x < 32) {
        float x = (threadIdx.x < 12) ? sm[threadIdx.x] : 0.f;
#pragma unroll
        for (int o = 16; o; o >>= 1) x += __shfl_xor_sync(0xFFFFFFFFu, x, o);
        if (threadIdx.x == 0) sm[12] = x;
    }
    __syncthreads();
    float r = sm[12];
    __syncthreads();
    return r;
}

// attention: logits + softmax + context.  grid = 64 (one block per batch), 384 threads
__global__ __launch_bounds__(384) void k_att(const float* __restrict__ src,
                                             const float* __restrict__ wscore) {
    __shared__ float proj_sh[HH];
    __shared__ float wsc_sh[HH];
    __shared__ float alpha_sh[LL];
    __shared__ float red_sh[16];
    int b = blockIdx.x;
    int tid = threadIdx.x;

    for (int j = tid; j < HH; j += 384) {
        proj_sh[j] = g_proj[(b << 9) + j];
        wsc_sh[j] = wscore[j];
    }
    __syncthreads();

    // logit for l = tid
    int l = tid;
    float lg = 0.f;
    const float* sf = g_srcfT + (size_t)b * HH * LL + l;
#pragma unroll 4
    for (int h = 0; h < HH; h++) {
        float v = sf[(size_t)h * LL] + proj_sh[h];
        lg += tanh_acc(v) * wsc_sh[h];
    }

    float mx = blk_red_max(lg, red_sh);
    float e = __expf(lg - mx);
    float s = blk_red_sum(e, red_sh);
    alpha_sh[l] = e * __fdividef(1.f, s);
    __syncthreads();

    // context[c] = sum_l alpha[l] * src[b][l][c]
    for (int c = tid; c < CC; c += 384) {
        float acc = 0.f;
        const float* sp = src + (size_t)b * LL * CC + c;
#pragma unroll 4
        for (int ll = 0; ll < LL; ll++) acc += alpha_sh[ll] * sp[(size_t)ll * CC];
        g_ctx[(b << 9) + c] = acc;
    }
}

// LSTM gates + cell update. grid (32 unit-tiles of 16, 4 batch-tiles of 16), 256 thr.
// thread: u = bx*16 + (tid&15); b = by*16 + (tid>>4). acc = 4 gates of one (u,b).
__global__ __launch_bounds__(256) void k_lstm(int t) {
    __shared__ float xs[16][32];
    int tid = threadIdx.x;
    int u = blockIdx.x * 16 + (tid & 15);
    int bsel = tid >> 4;
    int b = blockIdx.y * 16 + bsel;
    const float* hin = g_hbuf[t & 1];
    float* hout = g_hbuf[(t + 1) & 1];

    float4 b4 = *(const float4*)&g_bperm[u << 2];
    float a0 = b4.x, a1 = b4.y, a2 = b4.z, a3 = b4.w;

    for (int k0 = 0; k0 < KX; k0 += 32) {
        // stage x tile: 16 batches x 32 k
        for (int q = tid; q < 512; q += 256) {
            int bb = q >> 5, kk = q & 31;
            int b2 = (blockIdx.y << 4) + bb;
            int k = k0 + kk;
            float v;
            if (k < CC)            v = g_ctx[(b2 << 9) + k];
            else if (k < CC + EE)  v = g_emb[((size_t)(b2 * TT + t) << 8) + (k - CC)];
            else                   v = hin[(b2 << 9) + (k - CC - EE)];
            xs[bb][kk] = v;
        }
        __syncthreads();
        const float* wrow = g_Wt + (size_t)k0 * G4 + (u << 2);
#pragma unroll 8
        for (int kk = 0; kk < 32; kk++) {
            float4 w4 = *(const float4*)(wrow + (size_t)kk * G4);
            float xv = xs[bsel][kk];
            a0 += w4.x * xv; a1 += w4.y * xv; a2 += w4.z * xv; a3 += w4.w * xv;
        }
        __syncthreads();
    }

    float ig = sigm(a0);
    float fg = sigm(a1);
    float gg = tanh_acc(a2);
    float og = sigm(a3);
    int hc = (b << 9) + u;
    float cn = fg * g_c[hc] + ig * gg;
    float hn = og * tanh_acc(cn);
    g_c[hc] = cn;
    hout[hc] = hn;
    g_hs[((size_t)(b * TT + t) << 9) + u] = hn;
}

// final: probs[m][n] = sum_k hs[m][k]*WgenT[k][n] + bgen[n]; m = b*T+t (8128 rows)
// grid (127 m-tiles of 64, 4 n-tiles of 64), 256 threads, 4x4 microtile
__global__ __launch_bounds__(256) void k_out(const float* __restrict__ bgen,
                                             float* __restrict__ out) {
    __shared__ __align__(16) float Ash[16][68];
    __shared__ __align__(16) float Bsh[16][68];
    int m0 = blockIdx.x * 64;
    int n0 = blockIdx.y * 64;
    int tid = threadIdx.x;
    int r  = tid >> 2;
    int kq = (tid & 3) << 2;
    int bkk = tid >> 4;          // 0..15 (k for B tile)
    int nq  = (tid & 15) << 2;   // 0..60
    int tm = tid & 15;
    int tn = tid >> 4;
    float acc[4][4];
#pragma unroll
    for (int i = 0; i < 4; i++)
#pragma unroll
        for (int j = 0; j < 4; j++) acc[i][j] = 0.f;

    for (int k0 = 0; k0 < HH; k0 += 16) {
        float4 a4 = *(const float4*)&g_hs[(size_t)(m0 + r) * HH + k0 + kq];
        Ash[kq + 0][r] = a4.x; Ash[kq + 1][r] = a4.y; Ash[kq + 2][r] = a4.z; Ash[kq + 3][r] = a4.w;
#pragma unroll
        for (int j = 0; j < 4; j++) {
            int n = n0 + nq + j;
            Bsh[bkk][nq + j] = (n < NC) ? g_WgenT[(size_t)(k0 + bkk) * NC + n] : 0.f;
        }
        __syncthreads();
#pragma unroll
        for (int kk = 0; kk < 16; kk++) {
            float4 av4 = *(const float4*)&Ash[kk][tm << 2];
            float4 bv4 = *(const float4*)&Bsh[kk][tn << 2];
            float av[4] = {av4.x, av4.y, av4.z, av4.w};
            float bv[4] = {bv4.x, bv4.y, bv4.z, bv4.w};
#pragma unroll
            for (int i = 0; i < 4; i++)
#pragma unroll
                for (int j = 0; j < 4; j++) acc[i][j] += av[i] * bv[j];
        }
        __syncthreads();
    }
#pragma unroll
    for (int i = 0; i < 4; i++) {
        int m = m0 + (tm << 2) + i;
#pragma unroll
        for (int j = 0; j < 4; j++) {
            int n = n0 + (tn << 2) + j;
            if (n < NC) out[(size_t)m * NC + n] = acc[i][j] + bgen[n];
        }
    }
}

// ---------------- launch ----------------
extern "C" void kernel_launch(void* const* d_in, const int* in_sizes, int n_in,
                              void* d_out, int out_size) {
    const float* src       = (const float*)d_in[0];
    const int*   text      = (const int*)d_in[1];
    const float* emb_table = (const float*)d_in[2];
    const float* Wi2h      = (const float*)d_in[3];
    const float* Wh2h      = (const float*)d_in[4];
    const float* bh2h      = (const float*)d_in[5];
    const float* wscore    = (const float*)d_in[6];
    const float* W_ih      = (const float*)d_in[7];
    const float* b_ih      = (const float*)d_in[8];
    const float* W_hh      = (const float*)d_in[9];
    const float* b_hh      = (const float*)d_in[10];
    const float* Wgen      = (const float*)d_in[11];
    const float* bgen      = (const float*)d_in[12];
    float* out = (float*)d_out;
    (void)in_sizes; (void)n_in; (void)out_size;
    (void)Wh2h;

    k_init<<<(BB * HH + 255) / 256, 256>>>();
    k_prep_w<<<(KX * G4 + 255) / 256, 256>>>(W_ih, b_ih, W_hh, b_hh);
    k_prep_wh<<<(HH * HH + 255) / 256, 256>>>(Wh2h);
    k_prep_wgen<<<(HH * NC + 255) / 256, 256>>>(Wgen);
    k_emb<<<(BB * TT * EE + 255) / 256, 256>>>(text, emb_table);
    k_srcfeat<<<dim3(LL / 64, HH / 64, BB), 256>>>(src, Wi2h);

    for (int t = 0; t < TT; t++) {
        k_proj<<<128, 256>>>(bh2h, t);
        k_att<<<BB, 384>>>(src, wscore);
        k_lstm<<<dim3(32, 4), 256>>>(t);
    }

    k_out<<<dim3(127, 4), 256>>>(bgen, out);
}

// round 11
// speedup vs baseline: 5.7656x; 5.7656x over previous
#include <cuda_runtime.h>
#include <cuda_bf16.h>
#include <math.h>

#define BB 64
#define LL 384
#define CC 512
#define HH 512
#define EE 256
#define NC 250
#define TT 127
#define KX 1280     // C + E + H
#define G4 2048     // 4*H
#define KSPLIT 8
#define KSLICE 160  // KX / KSPLIT

// ---------------- device scratch ----------------
__device__ __align__(16) float g_srcfT[(size_t)BB * HH * LL];   // [b][h][l]
__device__ __align__(16) float g_Wt[(size_t)KX * G4];           // [k][u*4+g]
__device__ __align__(16) float g_bperm[G4];
__device__ __align__(16) float g_WgenT[HH * NC];                // [k][n]
__device__ __align__(16) float g_embT[(size_t)TT * EE * BB];    // [t][e][b]
__device__ __align__(16) float g_h[BB * HH];                    // [b][u]
__device__ __align__(16) float g_hT[HH * BB];                   // [u][b]
__device__ __align__(16) float g_cT[HH * BB];                   // [u][b]
__device__ __align__(16) float g_proj[BB * HH];
__device__ __align__(16) float g_lgp[4 * BB * LL];              // score partials
__device__ __align__(16) float g_X[CC * BB];                    // context transposed [c][b]
__device__ __align__(16) float g_gp[(size_t)KSPLIT * G4 * BB];  // gate partials
__device__ __align__(16) float g_hs[(size_t)BB * TT * HH];

// ---------------- math ----------------
__device__ __forceinline__ float tanh_fast(float x) {
    float y;
    asm("tanh.approx.f32 %0, %1;" : "=f"(y) : "f"(x));
    return y;
}
__device__ __forceinline__ float tanh_acc(float x) {
    float a = fabsf(x);
    float e = __expf(-2.0f * a);
    float r = __fdividef(1.0f - e, 1.0f + e);
    return copysignf(r, x);
}
__device__ __forceinline__ float sigm(float x) {
    return __fdividef(1.0f, 1.0f + __expf(-x));
}

// ---------------- prep ----------------
__global__ void k_init() {
    int i = blockIdx.x * 256 + threadIdx.x;
    if (i < BB * HH) { g_h[i] = 0.f; g_hT[i] = 0.f; g_cT[i] = 0.f; }
}

__global__ void k_prep_w(const float* __restrict__ W_ih, const float* __restrict__ b_ih,
                         const float* __restrict__ W_hh, const float* __restrict__ b_hh) {
    int idx = blockIdx.x * blockDim.x + threadIdx.x;
    if (idx >= KX * G4) return;
    int k = idx >> 11;
    int col = idx & (G4 - 1);
    int u = col >> 2;
    int g = col & 3;
    int row = g * HH + u;                      // PyTorch gate order i,f,g,o
    float v = (k < CC + EE) ? W_ih[(size_t)row * (CC + EE) + k]
                            : W_hh[(size_t)row * HH + (k - (CC + EE))];
    g_Wt[idx] = v;
    if (k == 0) g_bperm[col] = b_ih[row] + b_hh[row];
}

__global__ void k_prep_wgen(const float* __restrict__ Wgen) {
    int idx = blockIdx.x * blockDim.x + threadIdx.x;
    if (idx >= HH * NC) return;
    int k = idx / NC, n = idx - k * NC;
    g_WgenT[idx] = Wgen[(size_t)n * HH + k];
}

__global__ void k_prep_embT(const int* __restrict__ text, const float* __restrict__ emb_table) {
    int idx = blockIdx.x * blockDim.x + threadIdx.x;
    if (idx >= TT * EE * BB) return;
    int b = idx & (BB - 1);
    int e = (idx >> 6) & (EE - 1);
    int t = idx >> 14;
    int tok = text[b * TT + t];
    g_embT[idx] = emb_table[(size_t)tok * EE + e];
}

// src_featT[b][h][l] = sum_c Wi2h[h][c] * src[b][l][c]
__global__ __launch_bounds__(256) void k_srcfeat(const float* __restrict__ src,
                                                 const float* __restrict__ Wi2h) {
    __shared__ __align__(16) float Wsh[16][68];
    __shared__ __align__(16) float Ssh[16][68];
    int l0 = blockIdx.x * 64;
    int h0 = blockIdx.y * 64;
    int b  = blockIdx.z;
    int tid = threadIdx.x;
    int r  = tid >> 2;
    int kq = (tid & 3) << 2;
    int th = tid & 15;
    int tl = tid >> 4;
    float acc[4][4];
#pragma unroll
    for (int i = 0; i < 4; i++)
#pragma unroll
        for (int j = 0; j < 4; j++) acc[i][j] = 0.f;

    const float* srow = src + ((size_t)b * LL + l0 + r) * CC;
    const float* wrow = Wi2h + (size_t)(h0 + r) * CC;

    for (int k0 = 0; k0 < CC; k0 += 16) {
        float4 w4 = *(const float4*)(wrow + k0 + kq);
        float4 s4 = *(const float4*)(srow + k0 + kq);
        Wsh[kq + 0][r] = w4.x; Wsh[kq + 1][r] = w4.y; Wsh[kq + 2][r] = w4.z; Wsh[kq + 3][r] = w4.w;
        Ssh[kq + 0][r] = s4.x; Ssh[kq + 1][r] = s4.y; Ssh[kq + 2][r] = s4.z; Ssh[kq + 3][r] = s4.w;
        __syncthreads();
#pragma unroll
        for (int kk = 0; kk < 16; kk++) {
            float4 a4 = *(const float4*)&Wsh[kk][th << 2];
            float4 b4 = *(const float4*)&Ssh[kk][tl << 2];
            float av[4] = {a4.x, a4.y, a4.z, a4.w};
            float bv[4] = {b4.x, b4.y, b4.z, b4.w};
#pragma unroll
            for (int i = 0; i < 4; i++)
#pragma unroll
                for (int j = 0; j < 4; j++) acc[i][j] += av[i] * bv[j];
        }
        __syncthreads();
    }
#pragma unroll
    for (int i = 0; i < 4; i++) {
        float4 o4 = make_float4(acc[i][0], acc[i][1], acc[i][2], acc[i][3]);
        *(float4*)&g_srcfT[((size_t)b * HH + h0 + (th << 2) + i) * LL + l0 + (tl << 2)] = o4;
    }
}

// ---------------- per-step kernels ----------------
// proj[b][j] = Wh2h[j][:] . h[b][:] + bh2h[j]; warp-per-row GEMV
// grid (32 j-tiles of 16, 4 b-tiles of 16), 256 thr = 8 warps, 2 j per warp
__global__ __launch_bounds__(256) void k_proj(const float* __restrict__ Wh2h,
                                              const float* __restrict__ bh2h) {
    __shared__ float hsh[16][HH];
    int j0 = blockIdx.x << 4;
    int b0 = blockIdx.y << 4;
    int tid = threadIdx.x;
    int w = tid >> 5, lane = tid & 31;
    for (int i = tid; i < 16 * HH; i += 256)
        hsh[i >> 9][i & 511] = g_h[(b0 + (i >> 9)) * HH + (i & 511)];
    __syncthreads();
#pragma unroll
    for (int jj = 0; jj < 2; jj++) {
        int j = j0 + w * 2 + jj;
        float wreg[16];
        const float* wr = Wh2h + (size_t)j * HH;
#pragma unroll
        for (int i = 0; i < 16; i++) wreg[i] = wr[lane + i * 32];
        for (int bb = 0; bb < 16; bb++) {
            float acc = 0.f;
#pragma unroll
            for (int i = 0; i < 16; i++) acc += wreg[i] * hsh[bb][lane + i * 32];
#pragma unroll
            for (int o = 16; o; o >>= 1) acc += __shfl_xor_sync(0xFFFFFFFFu, acc, o);
            if (lane == 0) g_proj[(b0 + bb) * HH + j] = acc + bh2h[j];
        }
    }
}

// score partials: grid (4 h-chunks x 64 b), 384 thr, thread = l
__global__ __launch_bounds__(384) void k_score(const float* __restrict__ wscore) {
    __shared__ float psh[128];
    __shared__ float wsh[128];
    int h0 = blockIdx.x << 7;
    int b = blockIdx.y;
    int tid = threadIdx.x;
    if (tid < 128) {
        psh[tid] = g_proj[(b << 9) + h0 + tid];
        wsh[tid] = wscore[h0 + tid];
    }
    __syncthreads();
    float lg = 0.f;
    const float* sf = g_srcfT + ((size_t)b * HH + h0) * LL + tid;
#pragma unroll 8
    for (int h = 0; h < 128; h++)
        lg += tanh_fast(sf[(size_t)h * LL] + psh[h]) * wsh[h];
    g_lgp[(blockIdx.x * BB + b) * LL + tid] = lg;
}

// softmax (redundant per block) + context: grid (4 c-chunks x 64 b), 128 thr
__global__ __launch_bounds__(128) void k_ctx(const float* __restrict__ src) {
    __shared__ float lg[LL];
    __shared__ float alpha[LL];
    __shared__ float red[4];
    __shared__ float bc[2];
    int c0 = blockIdx.x << 7;
    int b = blockIdx.y;
    int tid = threadIdx.x;
    const float* lp = g_lgp + b * LL;
    for (int l = tid; l < LL; l += 128)
        lg[l] = lp[l] + lp[BB * LL + l] + lp[2 * BB * LL + l] + lp[3 * BB * LL + l];
    __syncthreads();
    float m = fmaxf(fmaxf(lg[tid], lg[tid + 128]), lg[tid + 256]);
#pragma unroll
    for (int o = 16; o; o >>= 1) m = fmaxf(m, __shfl_xor_sync(0xFFFFFFFFu, m, o));
    if ((tid & 31) == 0) red[tid >> 5] = m;
    __syncthreads();
    if (tid == 0) bc[0] = fmaxf(fmaxf(red[0], red[1]), fmaxf(red[2], red[3]));
    __syncthreads();
    float mx = bc[0];
    float s = 0.f;
    for (int l = tid; l < LL; l += 128) {
        float e = __expf(lg[l] - mx);
        alpha[l] = e;
        s += e;
    }
#pragma unroll
    for (int o = 16; o; o >>= 1) s += __shfl_xor_sync(0xFFFFFFFFu, s, o);
    if ((tid & 31) == 0) red[tid >> 5] = s;
    __syncthreads();
    if (tid == 0) bc[1] = red[0] + red[1] + red[2] + red[3];
    __syncthreads();
    float inv = __fdividef(1.f, bc[1]);
    int c = c0 + tid;
    float acc = 0.f;
    const float* sp = src + (size_t)b * LL * CC + c;
#pragma unroll 8
    for (int l = 0; l < LL; l++) acc += alpha[l] * sp[(size_t)l * CC];
    g_X[c * BB + b] = acc * inv;     // transposed for the gate GEMM
}

// gate GEMM: gp[ks][m=2048][n=64] partial over K slice. grid (16 m-tiles, 8 k-slices)
__global__ __launch_bounds__(256) void k_gemm_lstm(int t) {
    __shared__ __align__(16) float Wsh[16][128];
    __shared__ __align__(16) float Xsh[16][64];
    int m0 = blockIdx.x << 7;
    int k0b = blockIdx.y * KSLICE;
    int tid = threadIdx.x;
    int tx = tid & 15;          // n micro: 4 cols
    int ty = tid >> 4;          // m micro: 8 rows
    int srow = tid >> 4;        // staging row 0..15
    int wcol = (tid & 15) << 3; // W staging: 8 floats
    int xcol = (tid & 15) << 2; // X staging: 4 floats
    float acc[8][4];
#pragma unroll
    for (int i = 0; i < 8; i++)
#pragma unroll
        for (int j = 0; j < 4; j++) acc[i][j] = 0.f;

    for (int kc = 0; kc < KSLICE; kc += 16) {
        int k0 = k0b + kc;
        const float* wp = g_Wt + (size_t)(k0 + srow) * G4 + m0 + wcol;
        *(float4*)&Wsh[srow][wcol]     = *(const float4*)wp;
        *(float4*)&Wsh[srow][wcol + 4] = *(const float4*)(wp + 4);
        int r = k0 + srow;
        const float* xr = (r < CC) ? (g_X + r * BB)
                        : (r < CC + EE) ? (g_embT + ((size_t)t * EE + (r - CC)) * BB)
                                        : (g_hT + (r - CC - EE) * BB);
        *(float4*)&Xsh[srow][xcol] = *(const float4*)(xr + xcol);
        __syncthreads();
#pragma unroll
        for (int kk = 0; kk < 16; kk++) {
            float4 a0 = *(const float4*)&Wsh[kk][ty << 3];
            float4 a1 = *(const float4*)&Wsh[kk][(ty << 3) + 4];
            float4 bx = *(const float4*)&Xsh[kk][tx << 2];
            float av[8] = {a0.x, a0.y, a0.z, a0.w, a1.x, a1.y, a1.z, a1.w};
            float bv[4] = {bx.x, bx.y, bx.z, bx.w};
#pragma unroll
            for (int i = 0; i < 8; i++)
#pragma unroll
                for (int j = 0; j < 4; j++) acc[i][j] += av[i] * bv[j];
        }
        __syncthreads();
    }
    float* op = g_gp + ((size_t)blockIdx.y * G4 + m0 + (ty << 3)) * BB + (tx << 2);
#pragma unroll
    for (int i = 0; i < 8; i++)
        *(float4*)(op + (size_t)i * BB) = make_float4(acc[i][0], acc[i][1], acc[i][2], acc[i][3]);
}

// cell update: combine K-split partials, activations, write h / hT / cT / hs
__global__ __launch_bounds__(256) void k_cell(int t) {
    int idx = blockIdx.x * 256 + threadIdx.x;   // 0..32767
    int b = idx & (BB - 1);
    int u = idx >> 6;
    float4 bias = *(const float4*)&g_bperm[u << 2];
    float a0 = bias.x, a1 = bias.y, a2 = bias.z, a3 = bias.w;
    const float* gp = g_gp + ((size_t)(u << 2)) * BB + b;
#pragma unroll
    for (int ks = 0; ks < KSPLIT; ks++) {
        const float* p = gp + (size_t)ks * G4 * BB;
        a0 += p[0];
        a1 += p[BB];
        a2 += p[2 * BB];
        a3 += p[3 * BB];
    }
    float ig = sigm(a0);
    float fg = sigm(a1);
    float gg = tanh_acc(a2);
    float og = sigm(a3);
    int uc = u * BB + b;
    float cn = fg * g_cT[uc] + ig * gg;
    float hn = og * tanh_acc(cn);
    g_cT[uc] = cn;
    g_hT[uc] = hn;
    g_h[b * HH + u] = hn;
    g_hs[((size_t)(b * TT + t)) * HH + u] = hn;
}

// final: probs[m][n] = hs[m][:] . WgenT[:][n] + bgen[n]
__global__ __launch_bounds__(256) void k_out(const float* __restrict__ bgen,
                                             float* __restrict__ out) {
    __shared__ __align__(16) float Ash[16][68];
    __shared__ __align__(16) float Bsh[16][68];
    int m0 = blockIdx.x * 64;
    int n0 = blockIdx.y * 64;
    int tid = threadIdx.x;
    int r  = tid >> 2;
    int kq = (tid & 3) << 2;
    int bkk = tid >> 4;
    int nq  = (tid & 15) << 2;
    int tm = tid & 15;
    int tn = tid >> 4;
    float acc[4][4];
#pragma unroll
    for (int i = 0; i < 4; i++)
#pragma unroll
        for (int j = 0; j < 4; j++) acc[i][j] = 0.f;

    for (int k0 = 0; k0 < HH; k0 += 16) {
        float4 a4 = *(const float4*)&g_hs[(size_t)(m0 + r) * HH + k0 + kq];
        Ash[kq + 0][r] = a4.x; Ash[kq + 1][r] = a4.y; Ash[kq + 2][r] = a4.z; Ash[kq + 3][r] = a4.w;
#pragma unroll
        for (int j = 0; j < 4; j++) {
            int n = n0 + nq + j;
            Bsh[bkk][nq + j] = (n < NC) ? g_WgenT[(size_t)(k0 + bkk) * NC + n] : 0.f;
        }
        __syncthreads();
#pragma unroll
        for (int kk = 0; kk < 16; kk++) {
            float4 av4 = *(const float4*)&Ash[kk][tm << 2];
            float4 bv4 = *(const float4*)&Bsh[kk][tn << 2];
            float av[4] = {av4.x, av4.y, av4.z, av4.w};
            float bv[4] = {bv4.x, bv4.y, bv4.z, bv4.w};
#pragma unroll
            for (int i = 0; i < 4; i++)
#pragma unroll
                for (int j = 0; j < 4; j++) acc[i][j] += av[i] * bv[j];
        }
        __syncthreads();
    }
#pragma unroll
    for (int i = 0; i < 4; i++) {
        int m = m0 + (tm << 2) + i;
#pragma unroll
        for (int j = 0; j < 4; j++) {
            int n = n0 + (tn << 2) + j;
            if (n < NC) out[(size_t)m * NC + n] = acc[i][j] + bgen[n];
        }
    }
}

// ---------------- launch ----------------
extern "C" void kernel_launch(void* const* d_in, const int* in_sizes, int n_in,
                              void* d_out, int out_size) {
    const float* src       = (const float*)d_in[0];
    const int*   text      = (const int*)d_in[1];
    const float* emb_table = (const float*)d_in[2];
    const float* Wi2h      = (const float*)d_in[3];
    const float* Wh2h      = (const float*)d_in[4];
    const float* bh2h      = (const float*)d_in[5];
    const float* wscore    = (const float*)d_in[6];
    const float* W_ih      = (const float*)d_in[7];
    const float* b_ih      = (const float*)d_in[8];
    const float* W_hh      = (const float*)d_in[9];
    const float* b_hh      = (const float*)d_in[10];
    const float* Wgen      = (const float*)d_in[11];
    const float* bgen      = (const float*)d_in[12];
    float* out = (float*)d_out;
    (void)in_sizes; (void)n_in; (void)out_size;

    k_init<<<128, 256>>>();
    k_prep_w<<<(KX * G4 + 255) / 256, 256>>>(W_ih, b_ih, W_hh, b_hh);
    k_prep_wgen<<<(HH * NC + 255) / 256, 256>>>(Wgen);
    k_prep_embT<<<(TT * EE * BB + 255) / 256, 256>>>(text, emb_table);
    k_srcfeat<<<dim3(LL / 64, HH / 64, BB), 256>>>(src, Wi2h);

    for (int t = 0; t < TT; t++) {
        k_proj<<<dim3(32, 4), 256>>>(Wh2h, bh2h);
        k_score<<<dim3(4, BB), 384>>>(wscore);
        k_ctx<<<dim3(4, BB), 128>>>(src);
        k_gemm_lstm<<<dim3(16, KSPLIT), 256>>>(t);
        k_cell<<<128, 256>>>(t);
    }

    k_out<<<dim3(127, 4), 256>>>(bgen, out);
}